// round 1
// baseline (speedup 1.0000x reference)
#include <cuda_runtime.h>
#include <cstdint>

#define Bn 32
#define Cc 256
#define Hh 56
#define Wd 56
#define HW 3136                 // 56*56
#define NPIX (Bn*HW)            // 100352
#define NELEM ((size_t)Bn*Cc*HW)// 25690112
#define WWORDS 8                // 256 bits / 32

// ---- device scratch (no allocations allowed) ----
__device__ uint4              g_xbits[NPIX * 2];          // 8 u32 per pixel (3.2 MB)
__device__ uint32_t           g_wbits[Cc * 9 * WWORDS];   // 18432 u32
__device__ unsigned long long g_ysum[Cc];
__device__ unsigned long long g_ysumsq[Cc];
__device__ float              g_inv[Cc];
__device__ float              g_bias[Cc];
__device__ short              g_y[NELEM];                 // 51 MB int16 conv result

// ---------------------------------------------------------------------------
// Kernel 1: binarize x (NCHW) -> per-pixel 256-bit vectors
// thread = one (b, pixel); loops channels (coalesced across the warp in w)
// ---------------------------------------------------------------------------
__global__ void k_binarize_x(const float* __restrict__ x) {
    int gp = blockIdx.x * 256 + threadIdx.x;
    if (gp >= NPIX) return;
    int b = gp / HW;
    int p = gp - b * HW;
    const float* xp = x + (size_t)b * Cc * HW + p;

    uint32_t wrd[WWORDS];
#pragma unroll
    for (int j = 0; j < WWORDS; j++) {
        uint32_t v = 0;
#pragma unroll
        for (int l = 0; l < 32; l++) {
            float f = xp[(size_t)(j * 32 + l) * HW];
            v |= (f > 0.0f ? 1u : 0u) << l;
        }
        wrd[j] = v;
    }
    g_xbits[gp * 2 + 0] = make_uint4(wrd[0], wrd[1], wrd[2], wrd[3]);
    g_xbits[gp * 2 + 1] = make_uint4(wrd[4], wrd[5], wrd[6], wrd[7]);
}

// ---------------------------------------------------------------------------
// Kernel 2: binarize W (OIHW) -> per (o, tap) 256-bit vectors; zero stats
// thread = one u32 word: idx = (o*9 + tap)*8 + j
// ---------------------------------------------------------------------------
__global__ void k_binarize_w(const float* __restrict__ Wt) {
    int idx = blockIdx.x * 256 + threadIdx.x;
    if (idx < Cc) { g_ysum[idx] = 0ull; g_ysumsq[idx] = 0ull; }
    if (idx >= Cc * 9 * WWORDS) return;
    int j   = idx & 7;
    int tap = (idx >> 3) % 9;
    int o   = idx / (9 * WWORDS);
    uint32_t v = 0;
#pragma unroll
    for (int l = 0; l < 32; l++) {
        int i = j * 32 + l;
        float f = Wt[((size_t)o * Cc + i) * 9 + tap];
        v |= (f > 0.0f ? 1u : 0u) << l;
    }
    g_wbits[idx] = v;
}

// ---------------------------------------------------------------------------
// Kernel 3: XNOR-popcount conv + exact integer BN statistics
// grid = (pixel tiles, o, b); block = 256 threads, one output pixel each
// ---------------------------------------------------------------------------
__global__ void k_conv_stats() {
    const int o = blockIdx.y;
    const int b = blockIdx.z;
    const int p = blockIdx.x * 256 + threadIdx.x;

    __shared__ uint4 sw[18];          // 72 u32 = 9 taps * 8 words
    if (threadIdx.x < 18)
        sw[threadIdx.x] = ((const uint4*)(g_wbits + o * 72))[threadIdx.x];
    __syncthreads();

    int       ssum = 0;
    long long ssq  = 0;

    if (p < HW) {
        int h = p / Wd;
        int w = p - h * Wd;
        int acc = 0, nv = 0;
#pragma unroll
        for (int kh = 0; kh < 3; kh++) {
            int hh = h + kh - 1;
            if ((unsigned)hh >= (unsigned)Hh) continue;
#pragma unroll
            for (int kw = 0; kw < 3; kw++) {
                int wc = w + kw - 1;
                if ((unsigned)wc >= (unsigned)Wd) continue;
                int tap = kh * 3 + kw;
                const uint4 a0 = g_xbits[(b * HW + hh * Wd + wc) * 2 + 0];
                const uint4 a1 = g_xbits[(b * HW + hh * Wd + wc) * 2 + 1];
                const uint4 w0 = sw[tap * 2 + 0];
                const uint4 w1 = sw[tap * 2 + 1];
                acc += __popc(a0.x ^ w0.x) + __popc(a0.y ^ w0.y)
                     + __popc(a0.z ^ w0.z) + __popc(a0.w ^ w0.w)
                     + __popc(a1.x ^ w1.x) + __popc(a1.y ^ w1.y)
                     + __popc(a1.z ^ w1.z) + __popc(a1.w ^ w1.w);
                nv++;
            }
        }
        int yv = nv * Cc - 2 * acc;     // exact integer conv result
        g_y[((size_t)(b * Cc + o)) * HW + p] = (short)yv;
        ssum = yv;
        ssq  = (long long)yv * (long long)yv;
    }

    // block reduction (int sum fits 32-bit: 256*2304 < 2^31)
#pragma unroll
    for (int off = 16; off > 0; off >>= 1) {
        ssum += __shfl_down_sync(0xFFFFFFFFu, ssum, off);
        ssq  += __shfl_down_sync(0xFFFFFFFFu, ssq,  off);
    }
    __shared__ int       wsum[8];
    __shared__ long long wsq[8];
    int lane = threadIdx.x & 31, wid = threadIdx.x >> 5;
    if (lane == 0) { wsum[wid] = ssum; wsq[wid] = ssq; }
    __syncthreads();
    if (wid == 0) {
        int       s  = (lane < 8) ? wsum[lane] : 0;
        long long sq = (lane < 8) ? wsq[lane]  : 0;
#pragma unroll
        for (int off = 4; off > 0; off >>= 1) {
            s  += __shfl_down_sync(0xFFFFFFFFu, s,  off);
            sq += __shfl_down_sync(0xFFFFFFFFu, sq, off);
        }
        if (lane == 0) {
            atomicAdd(&g_ysum[o],   (unsigned long long)(long long)s);
            atomicAdd(&g_ysumsq[o], (unsigned long long)sq);
        }
    }
}

// ---------------------------------------------------------------------------
// Kernel 4: finalize BN constants per channel
// ---------------------------------------------------------------------------
__global__ void k_finalize(const float* __restrict__ gamma,
                           const float* __restrict__ beta) {
    int c = threadIdx.x;
    const double n = (double)NPIX;
    double mean = (double)(long long)g_ysum[c] / n;
    double var  = (double)(long long)g_ysumsq[c] / n - mean * mean;
    float inv = gamma[c] / sqrtf((float)var + 1e-5f);
    g_inv[c]  = inv;
    g_bias[c] = beta[c] - (float)mean * inv;
}

// ---------------------------------------------------------------------------
// Kernel 5: fused BN apply + residual add, vectorized x4
// ---------------------------------------------------------------------------
__global__ void k_bn_add(const float* __restrict__ x, float* __restrict__ out) {
    size_t i4 = (size_t)blockIdx.x * 256 + threadIdx.x;
    if (i4 >= NELEM / 4) return;
    size_t base = i4 * 4;
    int c = (int)((base / HW) % Cc);      // HW % 4 == 0 -> uniform within vec4
    float inv = g_inv[c], bias = g_bias[c];
    short4 ys = ((const short4*)g_y)[i4];
    float4 xv = ((const float4*)x)[i4];
    float4 ov;
    ov.x = (float)ys.x * inv + bias + xv.x;
    ov.y = (float)ys.y * inv + bias + xv.y;
    ov.z = (float)ys.z * inv + bias + xv.z;
    ov.w = (float)ys.w * inv + bias + xv.w;
    ((float4*)out)[i4] = ov;
}

// ---------------------------------------------------------------------------
extern "C" void kernel_launch(void* const* d_in, const int* in_sizes, int n_in,
                              void* d_out, int out_size) {
    const float* x     = (const float*)d_in[0];
    const float* Wt    = (const float*)d_in[1];
    const float* gamma = (const float*)d_in[2];
    const float* beta  = (const float*)d_in[3];
    float* out = (float*)d_out;

    // 1) binarize x: 100352 pixels
    k_binarize_x<<<(NPIX + 255) / 256, 256>>>(x);

    // 2) binarize W + zero stats: 18432 words
    k_binarize_w<<<(Cc * 9 * WWORDS + 255) / 256, 256>>>(Wt);

    // 3) conv + stats: (13 pixel tiles, 256 out channels, 32 batch)
    dim3 gc((HW + 255) / 256, Cc, Bn);
    k_conv_stats<<<gc, 256>>>();

    // 4) finalize BN constants
    k_finalize<<<1, Cc>>>(gamma, beta);

    // 5) epilogue
    size_t n4 = NELEM / 4;
    k_bn_add<<<(unsigned)((n4 + 255) / 256), 256>>>(x, out);
}

// round 2
// speedup vs baseline: 1.1696x; 1.1696x over previous
#include <cuda_runtime.h>
#include <cstdint>

#define Bn 32
#define Cc 256
#define Hh 56
#define Wd 56
#define HW 3136                 // 56*56
#define NPIX (Bn*HW)            // 100352
#define NELEM ((size_t)Bn*Cc*HW)// 25690112

// ---- device scratch (no allocations allowed) ----
__device__ uint4              g_xbits[NPIX * 2];        // 8 u32 per pixel (3.2 MB)
__device__ uint32_t           g_wbits[Cc * 9 * 8];      // 18432 u32
__device__ unsigned long long g_ysum[Cc];
__device__ unsigned long long g_ysumsq[Cc];
__device__ float              g_inv[Cc];
__device__ float              g_bias[Cc];
__device__ short              g_y[NELEM];               // 51 MB int16 conv result

// ---------------------------------------------------------------------------
// Kernel 1: binarize x (NCHW) -> per-pixel 256-bit vectors
// ---------------------------------------------------------------------------
__global__ void k_binarize_x(const float* __restrict__ x) {
    int gp = blockIdx.x * 256 + threadIdx.x;
    if (gp >= NPIX) return;
    int b = gp / HW;
    int p = gp - b * HW;
    const float* xp = x + (size_t)b * Cc * HW + p;

    uint32_t wrd[8];
#pragma unroll
    for (int j = 0; j < 8; j++) {
        uint32_t v = 0;
#pragma unroll
        for (int l = 0; l < 32; l++) {
            float f = xp[(size_t)(j * 32 + l) * HW];
            v |= (f > 0.0f ? 1u : 0u) << l;
        }
        wrd[j] = v;
    }
    g_xbits[gp * 2 + 0] = make_uint4(wrd[0], wrd[1], wrd[2], wrd[3]);
    g_xbits[gp * 2 + 1] = make_uint4(wrd[4], wrd[5], wrd[6], wrd[7]);
}

// ---------------------------------------------------------------------------
// Kernel 2: binarize W (OIHW) + zero stat accumulators
// ---------------------------------------------------------------------------
__global__ void k_binarize_w(const float* __restrict__ Wt) {
    int idx = blockIdx.x * 256 + threadIdx.x;
    if (idx < Cc) { g_ysum[idx] = 0ull; g_ysumsq[idx] = 0ull; }
    if (idx >= Cc * 9 * 8) return;
    int j   = idx & 7;
    int tap = (idx >> 3) % 9;
    int o   = idx / 72;
    uint32_t v = 0;
#pragma unroll
    for (int l = 0; l < 32; l++) {
        int i = j * 32 + l;
        float f = Wt[((size_t)o * Cc + i) * 9 + tap];
        v |= (f > 0.0f ? 1u : 0u) << l;
    }
    g_wbits[idx] = v;
}

// ---------------------------------------------------------------------------
// Kernel 3: XNOR-popcount conv.
// Block = 256 pixels x 128 output channels. x bits live in 72 registers,
// loaded ONCE per thread; weights stream from smem (warp-broadcast LDS).
// grid = (13 pixel tiles, 2 channel halves, 32 batch)
// ---------------------------------------------------------------------------
__global__ void __launch_bounds__(256, 2) k_conv() {
    const int p    = blockIdx.x * 256 + threadIdx.x;
    const int half = blockIdx.y;
    const int b    = blockIdx.z;

    __shared__ uint4 ws4[128 * 18];   // 128 ch * 72 u32 = 36 KB
    {
        const uint4* src = (const uint4*)(g_wbits + half * 128 * 72);
#pragma unroll
        for (int i = threadIdx.x; i < 128 * 18; i += 256) ws4[i] = src[i];
    }
    __syncthreads();
    if (p >= HW) return;

    const int h = p / Wd;
    const int w = p - h * Wd;

    // Load 9 neighbor bit-vectors into registers (clamped addr if invalid).
    uint32_t xr[72];
    unsigned vmask = 0;
#pragma unroll
    for (int kh = 0; kh < 3; kh++) {
#pragma unroll
        for (int kw = 0; kw < 3; kw++) {
            const int tap = kh * 3 + kw;
            const int hh = h + kh - 1, ww = w + kw - 1;
            const bool v = ((unsigned)hh < (unsigned)Hh) && ((unsigned)ww < (unsigned)Wd);
            const int  np = v ? (hh * Wd + ww) : p;
            const uint4 a0 = g_xbits[(b * HW + np) * 2 + 0];
            const uint4 a1 = g_xbits[(b * HW + np) * 2 + 1];
            xr[tap * 8 + 0] = a0.x; xr[tap * 8 + 1] = a0.y;
            xr[tap * 8 + 2] = a0.z; xr[tap * 8 + 3] = a0.w;
            xr[tap * 8 + 4] = a1.x; xr[tap * 8 + 5] = a1.y;
            xr[tap * 8 + 6] = a1.z; xr[tap * 8 + 7] = a1.w;
            vmask |= (v ? 1u : 0u) << tap;
        }
    }

    short* yout = g_y + ((size_t)(b * Cc + half * 128)) * HW + p;

#pragma unroll 2
    for (int o = 0; o < 128; o++) {
        const uint4* wp = ws4 + o * 18;
        int acc = 0;
#pragma unroll
        for (int tap = 0; tap < 9; tap++) {
            const uint4 w0 = wp[tap * 2 + 0];
            const uint4 w1 = wp[tap * 2 + 1];
            int t = __popc(xr[tap * 8 + 0] ^ w0.x) + __popc(xr[tap * 8 + 1] ^ w0.y)
                  + __popc(xr[tap * 8 + 2] ^ w0.z) + __popc(xr[tap * 8 + 3] ^ w0.w)
                  + __popc(xr[tap * 8 + 4] ^ w1.x) + __popc(xr[tap * 8 + 5] ^ w1.y)
                  + __popc(xr[tap * 8 + 6] ^ w1.z) + __popc(xr[tap * 8 + 7] ^ w1.w);
            // invalid tap contributes exactly 0 to y: force t=128
            acc += ((vmask >> tap) & 1u) ? t : 128;
        }
        yout[(size_t)o * HW] = (short)(9 * Cc - 2 * acc);   // 2304 - 2*acc
    }
}

// ---------------------------------------------------------------------------
// Kernel 3b: BN statistics over y (exact integer sums)
// grid = (256 channels, 32 batch); block 256 reduces 3136 int16 values
// ---------------------------------------------------------------------------
__global__ void k_stats() {
    const int c = blockIdx.x, b = blockIdx.y;
    const int4* yp = (const int4*)(g_y + ((size_t)(b * Cc + c)) * HW);

    int       s  = 0;
    long long sq = 0;
    for (int i = threadIdx.x; i < HW / 8; i += 256) {     // 392 int4s
        int4 v = yp[i];
        const int ww[4] = {v.x, v.y, v.z, v.w};
#pragma unroll
        for (int j = 0; j < 4; j++) {
            int lo = (short)(ww[j] & 0xFFFF);
            int hi = (short)(((unsigned)ww[j]) >> 16);
            s  += lo + hi;
            sq += (long long)lo * lo + (long long)hi * hi;
        }
    }
#pragma unroll
    for (int off = 16; off > 0; off >>= 1) {
        s  += __shfl_down_sync(0xFFFFFFFFu, s,  off);
        sq += __shfl_down_sync(0xFFFFFFFFu, sq, off);
    }
    __shared__ int       wsum[8];
    __shared__ long long wsq[8];
    const int lane = threadIdx.x & 31, wid = threadIdx.x >> 5;
    if (lane == 0) { wsum[wid] = s; wsq[wid] = sq; }
    __syncthreads();
    if (wid == 0) {
        int       s2  = (lane < 8) ? wsum[lane] : 0;
        long long sq2 = (lane < 8) ? wsq[lane]  : 0;
#pragma unroll
        for (int off = 4; off > 0; off >>= 1) {
            s2  += __shfl_down_sync(0xFFFFFFFFu, s2,  off);
            sq2 += __shfl_down_sync(0xFFFFFFFFu, sq2, off);
        }
        if (lane == 0) {
            atomicAdd(&g_ysum[c],   (unsigned long long)(long long)s2);
            atomicAdd(&g_ysumsq[c], (unsigned long long)sq2);
        }
    }
}

// ---------------------------------------------------------------------------
// Kernel 4: finalize BN constants
// ---------------------------------------------------------------------------
__global__ void k_finalize(const float* __restrict__ gamma,
                           const float* __restrict__ beta) {
    int c = threadIdx.x;
    const double n = (double)NPIX;
    double mean = (double)(long long)g_ysum[c] / n;
    double var  = (double)(long long)g_ysumsq[c] / n - mean * mean;
    float inv = gamma[c] / sqrtf((float)var + 1e-5f);
    g_inv[c]  = inv;
    g_bias[c] = beta[c] - (float)mean * inv;
}

// ---------------------------------------------------------------------------
// Kernel 5: fused BN apply + residual add, vectorized x4
// ---------------------------------------------------------------------------
__global__ void k_bn_add(const float* __restrict__ x, float* __restrict__ out) {
    size_t i4 = (size_t)blockIdx.x * 256 + threadIdx.x;
    if (i4 >= NELEM / 4) return;
    size_t base = i4 * 4;
    int c = (int)((base / HW) % Cc);
    float inv = g_inv[c], bias = g_bias[c];
    short4 ys = ((const short4*)g_y)[i4];
    float4 xv = ((const float4*)x)[i4];
    float4 ov;
    ov.x = (float)ys.x * inv + bias + xv.x;
    ov.y = (float)ys.y * inv + bias + xv.y;
    ov.z = (float)ys.z * inv + bias + xv.z;
    ov.w = (float)ys.w * inv + bias + xv.w;
    ((float4*)out)[i4] = ov;
}

// ---------------------------------------------------------------------------
extern "C" void kernel_launch(void* const* d_in, const int* in_sizes, int n_in,
                              void* d_out, int out_size) {
    const float* x     = (const float*)d_in[0];
    const float* Wt    = (const float*)d_in[1];
    const float* gamma = (const float*)d_in[2];
    const float* beta  = (const float*)d_in[3];
    float* out = (float*)d_out;

    k_binarize_x<<<(NPIX + 255) / 256, 256>>>(x);
    k_binarize_w<<<(Cc * 9 * 8 + 255) / 256, 256>>>(Wt);

    dim3 gc((HW + 255) / 256, 2, Bn);      // 13 x 2 x 32 = 832 blocks
    k_conv<<<gc, 256>>>();

    k_stats<<<dim3(Cc, Bn), 256>>>();
    k_finalize<<<1, Cc>>>(gamma, beta);

    size_t n4 = NELEM / 4;
    k_bn_add<<<(unsigned)((n4 + 255) / 256), 256>>>(x, out);
}